// round 2
// baseline (speedup 1.0000x reference)
#include <cuda_runtime.h>
#include <cstdint>
#include <cstddef>

#define BATCH 1024
#define LSEQ  512
#define DIM   64
#define KCAP  8
#define NEGV  (-65535.0f)
#define NTHREADS 512
#define XSS 68   // smem floats per X row (272B: conflict-free for both pass1 & pass2)
#define SSS 68   // smem floats per S row

// ---- shared memory layout (float offsets) ----
#define WT_OFF     0                           // W^T [512][8]            4096
#define XS_OFF     4096                        // X   [512][68]           34816
#define SS_OFF     (XS_OFF + LSEQ*XSS)         // S   [64][68]            4352
#define CPART_OFF  (SS_OFF + 64*SSS)           // pass1 partials [16][512] 8192
#define CP_OFF     (CPART_OFF + 16*512)        // C' [8][64]              512
#define CSPART_OFF (CP_OFF + 512)              // CS partials [4][512]    2048
#define CS_OFF     (CSPART_OFF + 4*512)        // Cs / high [8][64]       512
#define SCALE_OFF  (CS_OFF + 512)              // squash scale [64]       64
#define HST_OFF    (SCALE_OFF + 64)            // hs^T [64][8]            512
#define SMEM_FLOATS (HST_OFF + 512)            // = 55104 floats
#define SMEM_BYTES  (SMEM_FLOATS * 4)          // = 220416 B  (< 227KB)

__device__ float g_B[KCAP * LSEQ];                 // routing logits (shared across batch)
__device__ float g_scratch[BATCH * KCAP * LSEQ];   // per-batch deltas (16MB)
__device__ float g_part[64 * KCAP * LSEQ];         // stage-1 reduction partials (1MB)

__device__ __forceinline__ void cp_async16(uint32_t sa, const void* ga) {
    asm volatile("cp.async.cg.shared.global [%0], [%1], 16;" :: "r"(sa), "l"(ga));
}
__device__ __forceinline__ void cp_commit() {
    asm volatile("cp.async.commit_group;" ::: "memory");
}
__device__ __forceinline__ void cp_wait_n(int n) {
    switch (n) {
        case 0: asm volatile("cp.async.wait_group 0;" ::: "memory"); break;
        case 1: asm volatile("cp.async.wait_group 1;" ::: "memory"); break;
        case 2: asm volatile("cp.async.wait_group 2;" ::: "memory"); break;
        case 3: asm volatile("cp.async.wait_group 3;" ::: "memory"); break;
        case 4: asm volatile("cp.async.wait_group 4;" ::: "memory"); break;
        case 5: asm volatile("cp.async.wait_group 5;" ::: "memory"); break;
        case 6: asm volatile("cp.async.wait_group 6;" ::: "memory"); break;
        default: asm volatile("cp.async.wait_group 7;" ::: "memory"); break;
    }
}

// One routing iteration for one batch per CTA.
// LAST=1: write high to out, skip delta. LAST=0: write delta to g_scratch.
template<int LAST>
__global__ void __launch_bounds__(NTHREADS, 1)
route_kernel(const float* __restrict__ X, const float* __restrict__ Sg,
             const int* __restrict__ seqlen, float* __restrict__ out)
{
    extern __shared__ float sm[];
    const int tid  = threadIdx.x;
    const int w    = tid >> 5;
    const int lane = tid & 31;
    const int b    = blockIdx.x;
    const float* Xg = X + (size_t)b * (LSEQ * DIM);

    // S -> registers early (LDG latency overlapped with cp.async issue + softmax)
    float sreg[8];
    #pragma unroll
    for (int i = 0; i < 8; i++) sreg[i] = Sg[tid + i * 512];

    // Issue all X tile copies: 8 chunks of 64 rows, one commit group per chunk.
    uint32_t xs_base = (uint32_t)__cvta_generic_to_shared(&sm[XS_OFF]);
    #pragma unroll
    for (int c = 0; c < 8; c++) {
        #pragma unroll
        for (int h = 0; h < 2; h++) {
            int s   = tid + h * 512;          // sector id within chunk (0..1023)
            int row = s >> 4;
            int col = s & 15;                 // 16B column
            int l   = c * 64 + row;
            cp_async16(xs_base + (uint32_t)(l * (XSS * 4) + col * 16),
                       (const void*)(Xg + l * DIM + col * 4));
        }
        cp_commit();
    }

    // Stage S into padded smem
    #pragma unroll
    for (int i = 0; i < 8; i++) {
        int idx = tid + i * 512;
        int d = idx >> 6, o = idx & 63;
        sm[SS_OFF + d * SSS + o] = sreg[i];
    }

    const int slen = seqlen[b];

    // Masked softmax over L for the 8 capsule rows (warp k handles row k)
    if (w < 8) {
        const int k = w;
        float v[16];
        #pragma unroll
        for (int j = 0; j < 16; j++) {
            int l = lane + 32 * j;
            float bv = g_B[k * LSEQ + l];
            v[j] = (l < slen) ? bv : NEGV;
        }
        float m = v[0];
        #pragma unroll
        for (int j = 1; j < 16; j++) m = fmaxf(m, v[j]);
        #pragma unroll
        for (int off = 16; off > 0; off >>= 1)
            m = fmaxf(m, __shfl_xor_sync(0xffffffffu, m, off));
        float s = 0.f;
        #pragma unroll
        for (int j = 0; j < 16; j++) { v[j] = __expf(v[j] - m); s += v[j]; }
        #pragma unroll
        for (int off = 16; off > 0; off >>= 1)
            s += __shfl_xor_sync(0xffffffffu, s, off);
        float inv = 1.0f / s;
        #pragma unroll
        for (int j = 0; j < 16; j++) {
            int l = lane + 32 * j;
            sm[WT_OFF + l * 8 + k] = v[j] * inv;   // W^T[l][k]
        }
    }
    __syncthreads();   // W^T and S staged

    // ---- pass 1: C'[k][d] = sum_l W[k][l] * X[l][d]  (D_in space) ----
    // thread = (warp, lane=dpair); warp handles 4 rows per chunk; TK=8 in regs.
    float acc[8][2];
    #pragma unroll
    for (int k = 0; k < 8; k++) { acc[k][0] = 0.f; acc[k][1] = 0.f; }

    #pragma unroll
    for (int c = 0; c < 8; c++) {
        cp_wait_n(7 - c);
        __syncthreads();
        #pragma unroll
        for (int r = 0; r < 4; r++) {
            int l = c * 64 + w * 4 + r;
            float2 x = *(const float2*)&sm[XS_OFF + l * XSS + 2 * lane];
            const float* wr = &sm[WT_OFF + l * 8];
            float4 wa = *(const float4*)wr;
            float4 wb = *(const float4*)(wr + 4);
            acc[0][0] += wa.x * x.x; acc[0][1] += wa.x * x.y;
            acc[1][0] += wa.y * x.x; acc[1][1] += wa.y * x.y;
            acc[2][0] += wa.z * x.x; acc[2][1] += wa.z * x.y;
            acc[3][0] += wa.w * x.x; acc[3][1] += wa.w * x.y;
            acc[4][0] += wb.x * x.x; acc[4][1] += wb.x * x.y;
            acc[5][0] += wb.y * x.x; acc[5][1] += wb.y * x.y;
            acc[6][0] += wb.z * x.x; acc[6][1] += wb.z * x.y;
            acc[7][0] += wb.w * x.x; acc[7][1] += wb.w * x.y;
        }
    }

    #pragma unroll
    for (int k = 0; k < 8; k++) {
        sm[CPART_OFF + w * 512 + k * 64 + 2 * lane]     = acc[k][0];
        sm[CPART_OFF + w * 512 + k * 64 + 2 * lane + 1] = acc[k][1];
    }
    __syncthreads();
    {
        float s = 0.f;
        #pragma unroll
        for (int p = 0; p < 16; p++) s += sm[CPART_OFF + p * 512 + tid];
        sm[CP_OFF + tid] = s;                    // C'[k*64+d]
    }
    __syncthreads();

    // ---- Cs[k][o] = sum_d C'[k][d] * S[d][o]  (project to D_out) ----
    {
        int ds = tid >> 7, kk = (tid >> 4) & 7, oq = tid & 15;
        float4 a = make_float4(0.f, 0.f, 0.f, 0.f);
        #pragma unroll
        for (int dd = 0; dd < 16; dd++) {
            int d = ds * 16 + dd;
            float cv = sm[CP_OFF + kk * 64 + d];
            float4 sv = *(const float4*)&sm[SS_OFF + d * SSS + oq * 4];
            a.x += cv * sv.x; a.y += cv * sv.y; a.z += cv * sv.z; a.w += cv * sv.w;
        }
        *(float4*)&sm[CSPART_OFF + ds * 512 + kk * 64 + oq * 4] = a;
    }
    __syncthreads();
    {
        float s = 0.f;
        #pragma unroll
        for (int p = 0; p < 4; p++) s += sm[CSPART_OFF + p * 512 + tid];
        sm[CS_OFF + tid] = s;
    }
    __syncthreads();

    // ---- squash over the K (capsule) dim ----
    if (tid < 64) {
        float sq = 0.f;
        #pragma unroll
        for (int k = 0; k < 8; k++) {
            float cv = sm[CS_OFF + k * 64 + tid];
            sq += cv * cv;
        }
        sm[SCALE_OFF + tid] = (sq / (1.0f + sq)) * rsqrtf(sq + 1e-9f);
    }
    __syncthreads();

    float hv = sm[SCALE_OFF + (tid & 63)] * sm[CS_OFF + tid];
    sm[CS_OFF + tid] = hv;                       // high, in place
    if (LAST) {
        out[(size_t)b * 512 + tid] = hv;         // [B,K,Dout]
        return;
    }
    __syncthreads();

    // ---- hs[k][i] = sum_o high[k][o] * S[i][o] ----
    {
        int k = tid >> 6, i = tid & 63;
        float h = 0.f;
        #pragma unroll
        for (int oq = 0; oq < 16; oq++) {
            float4 cv = *(const float4*)&sm[CS_OFF + k * 64 + oq * 4];  // broadcast
            float4 sv = *(const float4*)&sm[SS_OFF + i * SSS + oq * 4];
            h += cv.x * sv.x + cv.y * sv.y + cv.z * sv.z + cv.w * sv.w;
        }
        sm[HST_OFF + i * 8 + k] = h;             // hs^T[i][k]
    }
    __syncthreads();

    // ---- pass 2: delta[k][l] = sum_i hs[k][i] * X[l][i] ----
    {
        float dacc[8];
        #pragma unroll
        for (int k = 0; k < 8; k++) dacc[k] = 0.f;
        #pragma unroll
        for (int iq = 0; iq < 16; iq++) {
            float4 x = *(const float4*)&sm[XS_OFF + tid * XSS + iq * 4];
            #pragma unroll
            for (int r = 0; r < 4; r++) {
                float xv = (r == 0) ? x.x : (r == 1) ? x.y : (r == 2) ? x.z : x.w;
                const float* hp = &sm[HST_OFF + (iq * 4 + r) * 8];
                float4 h0 = *(const float4*)hp;
                float4 h1 = *(const float4*)(hp + 4);
                dacc[0] += xv * h0.x; dacc[1] += xv * h0.y;
                dacc[2] += xv * h0.z; dacc[3] += xv * h0.w;
                dacc[4] += xv * h1.x; dacc[5] += xv * h1.y;
                dacc[6] += xv * h1.z; dacc[7] += xv * h1.w;
            }
        }
        float* sc = &g_scratch[(size_t)b * 4096 + tid];
        #pragma unroll
        for (int k = 0; k < 8; k++) sc[k * 512] = dacc[k];
    }
}

// Deterministic 2-stage cross-batch reduction of deltas into g_B
__global__ void reduce1_kernel() {
    int j = blockIdx.x * 256 + threadIdx.x;      // 0..4095
    int base = blockIdx.y * 16;
    float s = 0.f;
    #pragma unroll
    for (int i = 0; i < 16; i++) s += g_scratch[(size_t)(base + i) * 4096 + j];
    g_part[(size_t)blockIdx.y * 4096 + j] = s;
}
__global__ void reduce2_kernel() {
    int j = blockIdx.x * 256 + threadIdx.x;
    float s = 0.f;
    #pragma unroll
    for (int i = 0; i < 64; i++) s += g_part[(size_t)i * 4096 + j];
    g_B[j] += s;
}

extern "C" void kernel_launch(void* const* d_in, const int* in_sizes, int n_in,
                              void* d_out, int out_size)
{
    const float* X     = (const float*)d_in[0];  // low_capsule [1024,512,64]
    const float* Binit = (const float*)d_in[1];  // B_init [1,8,512]
    const float* S     = (const float*)d_in[2];  // S [64,64]
    const int*   seq   = (const int*)d_in[3];    // seq_len [1024,1]
    float* out = (float*)d_out;

    cudaFuncSetAttribute(route_kernel<0>, cudaFuncAttributeMaxDynamicSharedMemorySize, SMEM_BYTES);
    cudaFuncSetAttribute(route_kernel<1>, cudaFuncAttributeMaxDynamicSharedMemorySize, SMEM_BYTES);

    void* bptr = nullptr;
    cudaGetSymbolAddress(&bptr, g_B);
    cudaMemcpyAsync(bptr, Binit, KCAP * LSEQ * sizeof(float),
                    cudaMemcpyDeviceToDevice, 0);

    // iter 0
    route_kernel<0><<<BATCH, NTHREADS, SMEM_BYTES>>>(X, S, seq, out);
    reduce1_kernel<<<dim3(16, 64), 256>>>();
    reduce2_kernel<<<16, 256>>>();
    // iter 1
    route_kernel<0><<<BATCH, NTHREADS, SMEM_BYTES>>>(X, S, seq, out);
    reduce1_kernel<<<dim3(16, 64), 256>>>();
    reduce2_kernel<<<16, 256>>>();
    // iter 2 (final): writes high
    route_kernel<1><<<BATCH, NTHREADS, SMEM_BYTES>>>(X, S, seq, out);
}